// round 15
// baseline (speedup 1.0000x reference)
#include <cuda_runtime.h>
#include <cuda_fp16.h>
#include <stdint.h>

// GCNConvDGL: out = segment_sum(x[src] -> dst) @ W + bias
// CSR build + single fused agg∥GEMM kernel (16:1 interleave, tile flags).

#define N_NODES 50000
#define N_EDGES 800000
#define D       512
#define M_PAD   50048          // 391 * 128
#define NTILES  391            // M_PAD / 128
#define NAGG    25024          // M_PAD / 2  (2 nodes per agg block) = 1564*16
#define NGEMM   1564           // NTILES * 4
#define SCAN_NB 196            // ceil(50000 / 256)
#define HIST_NB 782            // ceil(200000 / 256)  (int4 edge chunks)
#define CONVX_NB 25000         // 25.6M elems / 4 per thread / 256 threads
#define CONVW_NB 1024          // 512*512/256

// ---------------- scratch (static device globals) ----------------
__device__ __half  g_x16[(size_t)N_NODES * D];  // 51.2 MB
__device__ __half  g_a[(size_t)M_PAD * D];      // 51.2 MB
__device__ __half  g_wt[(size_t)D * D];         // W^T fp16
__device__ int     g_cnt[N_NODES];              // zeroed by scan1 of PREVIOUS call (zero-init first call)
__device__ int     g_row[N_NODES + 1];
__device__ int     g_work[N_NODES];
__device__ int     g_csr[N_EDGES];
__device__ int     g_bsum[SCAN_NB];
__device__ int     g_ready[NTILES];             // per-tile agg completion count

// ---------------- PTX helpers ----------------
__device__ __forceinline__ uint32_t smem_u32(const void* p) {
    uint32_t a;
    asm("{ .reg .u64 t; cvta.to.shared.u64 t, %1; cvt.u32.u64 %0, t; }"
        : "=r"(a) : "l"(p));
    return a;
}
__device__ __forceinline__ void cp_async16(uint32_t saddr, const void* gaddr) {
    asm volatile("cp.async.cg.shared.global [%0], [%1], 16;"
                 :: "r"(saddr), "l"(gaddr) : "memory");
}
__device__ __forceinline__ void cp_commit() {
    asm volatile("cp.async.commit_group;" ::: "memory");
}
template <int N> __device__ __forceinline__ void cp_wait() {
    asm volatile("cp.async.wait_group %0;" :: "n"(N) : "memory");
}
__device__ __forceinline__ void ldm_x4(uint32_t* r, uint32_t saddr) {
    asm volatile("ldmatrix.sync.aligned.m8n8.x4.shared.b16 {%0,%1,%2,%3}, [%4];"
                 : "=r"(r[0]), "=r"(r[1]), "=r"(r[2]), "=r"(r[3])
                 : "r"(saddr));
}
__device__ __forceinline__ void mma_fp16(float* c, const uint32_t* a,
                                         uint32_t b0, uint32_t b1) {
    asm volatile(
        "mma.sync.aligned.m16n8k16.row.col.f32.f16.f16.f32 "
        "{%0,%1,%2,%3}, {%4,%5,%6,%7}, {%8,%9}, {%0,%1,%2,%3};"
        : "+f"(c[0]), "+f"(c[1]), "+f"(c[2]), "+f"(c[3])
        : "r"(a[0]), "r"(a[1]), "r"(a[2]), "r"(a[3]), "r"(b0), "r"(b1));
}
__device__ __forceinline__ float4 ld_cs_f4(const float* p) {
    float4 v;
    asm volatile("ld.global.cs.v4.f32 {%0, %1, %2, %3}, [%4];"
                 : "=f"(v.x), "=f"(v.y), "=f"(v.z), "=f"(v.w) : "l"(p));
    return v;
}
__device__ __forceinline__ int ld_acquire(const int* p) {
    int v;
    asm volatile("ld.acquire.gpu.s32 %0, [%1];" : "=r"(v) : "l"(p));
    return v;
}

// Warp-inclusive scan
__device__ __forceinline__ int warp_iscan(int v, int lane) {
    #pragma unroll
    for (int off = 1; off < 32; off <<= 1) {
        int t = __shfl_up_sync(0xFFFFFFFF, v, off);
        if (lane >= off) v += t;
    }
    return v;
}

__device__ __forceinline__ int block_escan256(int v, int tid, int* smem8, int* total) {
    const int lane = tid & 31, wid = tid >> 5;
    int inc = warp_iscan(v, lane);
    if (lane == 31) smem8[wid] = inc;
    __syncthreads();
    if (wid == 0) {
        int ws = (lane < 8) ? smem8[lane] : 0;
        ws = warp_iscan(ws, lane);
        if (lane < 8) smem8[lane] = ws;
    }
    __syncthreads();
    int woff = (wid > 0) ? smem8[wid - 1] : 0;
    *total = smem8[7];
    return inc - v + woff;
}

// ---------------------------------------------------------------------------
// FUSED: dst-histogram (blocks [0, HIST_NB)) || x fp32->fp16 convert (rest).
// Relies on g_cnt being zero on entry (zero-init first call; scan1 re-zeroes).
// ---------------------------------------------------------------------------
__global__ void __launch_bounds__(256) fused_hist_convx_kernel(
    const int* __restrict__ dst, const float* __restrict__ x)
{
    if (blockIdx.x < HIST_NB) {
        int t = blockIdx.x * 256 + threadIdx.x;
        if (t < N_EDGES / 4) {
            int4 d = __ldg((const int4*)dst + t);
            atomicAdd(&g_cnt[d.x], 1);
            atomicAdd(&g_cnt[d.y], 1);
            atomicAdd(&g_cnt[d.z], 1);
            atomicAdd(&g_cnt[d.w], 1);
        }
    } else {
        size_t i = ((size_t)(blockIdx.x - HIST_NB) * 256 + threadIdx.x) * 4;
        if (i < (size_t)N_NODES * D) {
            float4 v = ld_cs_f4(x + i);
            __half h[4] = {__float2half_rn(v.x), __float2half_rn(v.y),
                           __float2half_rn(v.z), __float2half_rn(v.w)};
            *(uint2*)(g_x16 + i) = *(uint2*)h;
        }
    }
}

// scan1: per-block exclusive scan of g_cnt; also RE-ZEROES g_cnt for the
// next call (deterministic: identical work every call).
__global__ void __launch_bounds__(256) scan1_kernel() {
    __shared__ int smem8[8];
    int tid = threadIdx.x;
    int i = blockIdx.x * 256 + tid;
    int v = 0;
    if (i < N_NODES) {
        v = g_cnt[i];
        g_cnt[i] = 0;
    }
    int total;
    int excl = block_escan256(v, tid, smem8, &total);
    if (i < N_NODES) g_row[i] = excl;
    if (tid == 0) g_bsum[blockIdx.x] = total;
}

// scan3b: every block redundantly scans the 196 block sums (replaces scan2),
// finalizes g_row/g_work, zeroes g_ready tile flags.
__global__ void __launch_bounds__(256) scan3_kernel() {
    __shared__ int smem8[8];
    __shared__ int s_excl[256];
    int tid = threadIdx.x;
    int v = (tid < SCAN_NB) ? g_bsum[tid] : 0;
    int total;
    int excl = block_escan256(v, tid, smem8, &total);
    s_excl[tid] = excl;
    __syncthreads();
    int boff = s_excl[blockIdx.x];

    int i = blockIdx.x * 256 + tid;
    if (i < N_NODES) {
        int r = g_row[i] + boff;
        g_row[i]  = r;
        g_work[i] = r;
    }
    if (i == 0) g_row[N_NODES] = N_EDGES;
    if (i < NTILES) g_ready[i] = 0;
}

// ---------------------------------------------------------------------------
// FUSED: CSR scatter (blocks [0, HIST_NB)) || W convert/transpose (rest).
// ---------------------------------------------------------------------------
__global__ void __launch_bounds__(256) fused_scatter_convw_kernel(
    const int* __restrict__ src, const int* __restrict__ dst,
    const float* __restrict__ W)
{
    if (blockIdx.x < HIST_NB) {
        int t = blockIdx.x * 256 + threadIdx.x;
        if (t < N_EDGES / 4) {
            int4 s = __ldg((const int4*)src + t);
            int4 d = __ldg((const int4*)dst + t);
            g_csr[atomicAdd(&g_work[d.x], 1)] = s.x;
            g_csr[atomicAdd(&g_work[d.y], 1)] = s.y;
            g_csr[atomicAdd(&g_work[d.z], 1)] = s.z;
            g_csr[atomicAdd(&g_work[d.w], 1)] = s.w;
        }
    } else {
        int idx = (blockIdx.x - HIST_NB) * 256 + threadIdx.x;
        if (idx < D * D) {
            int k = idx >> 9, n = idx & 511;
            g_wt[(size_t)n * D + k] = __float2half_rn(W[idx]);
        }
    }
}

// ---------------------------------------------------------------------------
// MEGA kernel: agg blocks and GEMM blocks interleaved 16:1.
//   bid % 17 < 16  -> agg block ab = (bid/17)*16 + bid%17   (2 nodes each)
//   bid % 17 == 16 -> gemm block g = bid/17                 (tile g>>2, ncol g&3)
// GEMM blocks spin on g_ready[tile] == 64 (released by agg blocks).
// ---------------------------------------------------------------------------
#define BK      32
#define KP      40                    // padded smem row stride (elements)
#define TILE_B  (128 * KP * 2)        // 10240 B per tile
#define STAGE_B (2 * TILE_B)          // A, B = 20480 B
#define STAGES  3
#define SMEM_TOTAL (STAGES * STAGE_B) // 61440 B
#define NK      (D / BK)              // 16

__global__ void __launch_bounds__(256, 2) mega_kernel(
    const float* __restrict__ bias,
    float* __restrict__ C)
{
    extern __shared__ char smem[];
    const int tid = threadIdx.x;
    const int r17 = blockIdx.x % 17;
    const int u   = blockIdx.x / 17;

    if (r17 < 16) {
        // ======================= AGG part =======================
        const int ab = u * 16 + r17;            // 0..25023
        const int wg = tid >> 7;                // 0 or 1
        const int wg_tid = tid & 127;
        const int node = ab * 2 + wg;           // < M_PAD

        float4 acc = make_float4(0.f, 0.f, 0.f, 0.f);
        if (node < N_NODES) {
            const int s0 = g_row[node];
            const int s1 = g_row[node + 1];
            int e = s0;
            for (; e + 7 < s1; e += 8) {
                int si[8];
                #pragma unroll
                for (int j = 0; j < 8; j++) si[j] = __ldg(&g_csr[e + j]);
                uint2 v[8];
                #pragma unroll
                for (int j = 0; j < 8; j++)
                    v[j] = __ldg((const uint2*)(g_x16 + (size_t)si[j] * D) + wg_tid);
                #pragma unroll
                for (int j = 0; j < 8; j++) {
                    float2 f0 = __half22float2(*(__half2*)&v[j].x);
                    float2 f1 = __half22float2(*(__half2*)&v[j].y);
                    acc.x += f0.x; acc.y += f0.y; acc.z += f1.x; acc.w += f1.y;
                }
            }
            for (; e < s1; e++) {
                int sa = __ldg(&g_csr[e]);
                uint2 v = __ldg((const uint2*)(g_x16 + (size_t)sa * D) + wg_tid);
                float2 f0 = __half22float2(*(__half2*)&v.x);
                float2 f1 = __half22float2(*(__half2*)&v.y);
                acc.x += f0.x; acc.y += f0.y; acc.z += f1.x; acc.w += f1.y;
            }
        }
        __half h[4] = {__float2half_rn(acc.x), __float2half_rn(acc.y),
                       __float2half_rn(acc.z), __float2half_rn(acc.w)};
        *(uint2*)(g_a + (size_t)node * D + wg_tid * 4) = *(uint2*)h;

        // release: all 256 threads' stores -> barrier -> fence -> count
        __syncthreads();
        if (tid == 0) {
            __threadfence();
            atomicAdd(&g_ready[ab >> 6], 1);
        }
        return;
    }

    // ======================= GEMM part =======================
    const int g = u;                           // 0..1563
    const int bm_tile = g >> 2;
    const int block_m = bm_tile * 128;
    const int block_n = (g & 3) * 128;

    // acquire: wait for all 64 agg blocks of this tile
    if (tid == 0) {
        while (ld_acquire(&g_ready[bm_tile]) < 64) __nanosleep(128);
    }
    __syncthreads();

    const uint32_t smem_base = smem_u32(smem);
    const int wid  = tid >> 5;
    const int lane = tid & 31;
    const int wm   = wid >> 2;
    const int wn   = wid & 3;

    auto load_chunk = [&](int kt, int stage) {
        const int k0 = kt * BK;
        const uint32_t sb = smem_base + stage * STAGE_B;
        #pragma unroll
        for (int it = 0; it < 4; it++) {
            const int cid  = it * 256 + tid;      // 0..1023
            const int tile = cid >> 9;            // 0..1
            const int rr   = (cid >> 2) & 127;
            const int c4   = cid & 3;
            const __half* gp;
            if (tile == 0) gp = g_a  + (size_t)(block_m + rr) * D;
            else           gp = g_wt + (size_t)(block_n + rr) * D;
            cp_async16(sb + tile * TILE_B + rr * (KP * 2) + c4 * 16,
                       gp + k0 + c4 * 8);
        }
        cp_commit();
    };

    float acc[4][4][4];
    #pragma unroll
    for (int i = 0; i < 4; i++)
        #pragma unroll
        for (int j = 0; j < 4; j++)
            #pragma unroll
            for (int e = 0; e < 4; e++)
                acc[i][j][e] = 0.f;

    load_chunk(0, 0);
    load_chunk(1, 1);

    const uint32_t row_off = (uint32_t)(lane & 15) * (KP * 2);
    const uint32_t k_lane  = (uint32_t)((lane >> 4) << 4);

    for (int kt = 0; kt < NK; kt++) {
        if (kt >= NK - 1) cp_wait<0>(); else cp_wait<1>();
        __syncthreads();
        if (kt + 2 < NK) load_chunk(kt + 2, (kt + 2) % STAGES);

        const uint32_t sb  = smem_base + (kt % STAGES) * STAGE_B;
        const uint32_t aF0 = sb + 0 * TILE_B + (wm * 64) * (KP * 2) + row_off;
        const uint32_t bF0 = sb + 1 * TILE_B + (wn * 32) * (KP * 2) + row_off;

        #pragma unroll
        for (int ks = 0; ks < 2; ks++) {
            const uint32_t koff = ks * 32 + k_lane;
            uint32_t bF[2][4];
            #pragma unroll
            for (int np = 0; np < 2; np++)
                ldm_x4(bF[np], bF0 + np * 16 * (KP * 2) + koff);
            #pragma unroll
            for (int mt = 0; mt < 4; mt++) {
                uint32_t aF[4];
                ldm_x4(aF, aF0 + mt * 16 * (KP * 2) + koff);
                #pragma unroll
                for (int nt = 0; nt < 4; nt++) {
                    const int np = nt >> 1, sel = nt & 1;
                    mma_fp16(acc[mt][nt], aF, bF[np][sel], bF[np][sel + 2]);
                }
            }
        }
    }

    #pragma unroll
    for (int nt = 0; nt < 4; nt++) {
        const int col = block_n + wn * 32 + nt * 8 + (lane & 3) * 2;
        const float2 bv = *(const float2*)(bias + col);
        #pragma unroll
        for (int mt = 0; mt < 4; mt++) {
            const int r0 = block_m + wm * 64 + mt * 16 + (lane >> 2);
            const int r1 = r0 + 8;
            if (r0 < N_NODES) {
                float2 o = make_float2(acc[mt][nt][0] + bv.x,
                                       acc[mt][nt][1] + bv.y);
                *(float2*)(C + (size_t)r0 * D + col) = o;
            }
            if (r1 < N_NODES) {
                float2 o = make_float2(acc[mt][nt][2] + bv.x,
                                       acc[mt][nt][3] + bv.y);
                *(float2*)(C + (size_t)r1 * D + col) = o;
            }
        }
    }
}

// ---------------------------------------------------------------------------
extern "C" void kernel_launch(void* const* d_in, const int* in_sizes, int n_in,
                              void* d_out, int out_size)
{
    const float* x      = (const float*)d_in[0];
    const float* weight = (const float*)d_in[1];
    const float* bias   = (const float*)d_in[2];
    const int*   src    = (const int*)d_in[3];
    const int*   dst    = (const int*)d_in[4];
    float*       out    = (float*)d_out;

    fused_hist_convx_kernel<<<HIST_NB + CONVX_NB, 256>>>(dst, x);
    scan1_kernel<<<SCAN_NB, 256>>>();
    scan3_kernel<<<SCAN_NB, 256>>>();
    fused_scatter_convw_kernel<<<HIST_NB + CONVW_NB, 256>>>(src, dst, weight);

    {
        static bool attr_set = false;
        if (!attr_set) {
            cudaFuncSetAttribute(mega_kernel,
                                 cudaFuncAttributeMaxDynamicSharedMemorySize,
                                 SMEM_TOTAL);
            attr_set = true;
        }
        mega_kernel<<<NGEMM * 17, 256, SMEM_TOTAL>>>(bias, out);
    }
}

// round 16
// speedup vs baseline: 2.0259x; 2.0259x over previous
#include <cuda_runtime.h>
#include <cuda_fp16.h>
#include <stdint.h>

// GCNConvDGL: out = segment_sum(x[src] -> dst) @ W + bias
// Fused-phase CSR build + fp16 gather-aggregation + single-product fp16 GEMM.

#define N_NODES 50000
#define N_EDGES 800000
#define D       512
#define M_PAD   50048          // 391 * 128
#define NTILES  391
#define SCAN_NB 196            // ceil(50000 / 256)
#define HIST_NB 782            // ceil(200000 / 256)  (int4 edge chunks)
#define CONVX_NB 25000         // 25.6M elems / 4 per thread / 256 threads
#define CONVW_NB 1024          // 512*512/256

// ---------------- scratch (static device globals) ----------------
__device__ __half  g_x16[(size_t)N_NODES * D];  // 51.2 MB
__device__ __half  g_a[(size_t)M_PAD * D];      // 51.2 MB
__device__ __half  g_wt[(size_t)D * D];         // W^T fp16
__device__ int     g_cnt[N_NODES];              // zero at entry (zero-init; scan1 re-zeroes)
__device__ int     g_row[N_NODES + 1];
__device__ int     g_work[N_NODES];
__device__ int     g_csr[N_EDGES];
__device__ int     g_bsum[SCAN_NB];

// ---------------- PTX helpers ----------------
__device__ __forceinline__ uint32_t smem_u32(const void* p) {
    uint32_t a;
    asm("{ .reg .u64 t; cvta.to.shared.u64 t, %1; cvt.u32.u64 %0, t; }"
        : "=r"(a) : "l"(p));
    return a;
}
__device__ __forceinline__ void cp_async16(uint32_t saddr, const void* gaddr) {
    asm volatile("cp.async.cg.shared.global [%0], [%1], 16;"
                 :: "r"(saddr), "l"(gaddr) : "memory");
}
__device__ __forceinline__ void cp_commit() {
    asm volatile("cp.async.commit_group;" ::: "memory");
}
template <int N> __device__ __forceinline__ void cp_wait() {
    asm volatile("cp.async.wait_group %0;" :: "n"(N) : "memory");
}
__device__ __forceinline__ void ldm_x4(uint32_t* r, uint32_t saddr) {
    asm volatile("ldmatrix.sync.aligned.m8n8.x4.shared.b16 {%0,%1,%2,%3}, [%4];"
                 : "=r"(r[0]), "=r"(r[1]), "=r"(r[2]), "=r"(r[3])
                 : "r"(saddr));
}
__device__ __forceinline__ void mma_fp16(float* c, const uint32_t* a,
                                         uint32_t b0, uint32_t b1) {
    asm volatile(
        "mma.sync.aligned.m16n8k16.row.col.f32.f16.f16.f32 "
        "{%0,%1,%2,%3}, {%4,%5,%6,%7}, {%8,%9}, {%0,%1,%2,%3};"
        : "+f"(c[0]), "+f"(c[1]), "+f"(c[2]), "+f"(c[3])
        : "r"(a[0]), "r"(a[1]), "r"(a[2]), "r"(a[3]), "r"(b0), "r"(b1));
}
__device__ __forceinline__ float4 ld_cs_f4(const float* p) {
    float4 v;
    asm volatile("ld.global.cs.v4.f32 {%0, %1, %2, %3}, [%4];"
                 : "=f"(v.x), "=f"(v.y), "=f"(v.z), "=f"(v.w) : "l"(p));
    return v;
}

// Warp-inclusive scan
__device__ __forceinline__ int warp_iscan(int v, int lane) {
    #pragma unroll
    for (int off = 1; off < 32; off <<= 1) {
        int t = __shfl_up_sync(0xFFFFFFFF, v, off);
        if (lane >= off) v += t;
    }
    return v;
}

__device__ __forceinline__ int block_escan256(int v, int tid, int* smem8, int* total) {
    const int lane = tid & 31, wid = tid >> 5;
    int inc = warp_iscan(v, lane);
    if (lane == 31) smem8[wid] = inc;
    __syncthreads();
    if (wid == 0) {
        int ws = (lane < 8) ? smem8[lane] : 0;
        ws = warp_iscan(ws, lane);
        if (lane < 8) smem8[lane] = ws;
    }
    __syncthreads();
    int woff = (wid > 0) ? smem8[wid - 1] : 0;
    *total = smem8[7];
    return inc - v + woff;
}

// ---------------------------------------------------------------------------
// FUSED: dst-histogram (blocks [0, HIST_NB)) || x fp32->fp16 convert (rest).
// ---------------------------------------------------------------------------
__global__ void __launch_bounds__(256) fused_hist_convx_kernel(
    const int* __restrict__ dst, const float* __restrict__ x)
{
    if (blockIdx.x < HIST_NB) {
        int t = blockIdx.x * 256 + threadIdx.x;
        if (t < N_EDGES / 4) {
            int4 d = __ldg((const int4*)dst + t);
            atomicAdd(&g_cnt[d.x], 1);
            atomicAdd(&g_cnt[d.y], 1);
            atomicAdd(&g_cnt[d.z], 1);
            atomicAdd(&g_cnt[d.w], 1);
        }
    } else {
        size_t i = ((size_t)(blockIdx.x - HIST_NB) * 256 + threadIdx.x) * 4;
        if (i < (size_t)N_NODES * D) {
            float4 v = ld_cs_f4(x + i);
            __half h[4] = {__float2half_rn(v.x), __float2half_rn(v.y),
                           __float2half_rn(v.z), __float2half_rn(v.w)};
            *(uint2*)(g_x16 + i) = *(uint2*)h;
        }
    }
}

// scan1: per-block exclusive scan of g_cnt; re-zeroes g_cnt for next call.
__global__ void __launch_bounds__(256) scan1_kernel() {
    __shared__ int smem8[8];
    int tid = threadIdx.x;
    int i = blockIdx.x * 256 + tid;
    int v = 0;
    if (i < N_NODES) {
        v = g_cnt[i];
        g_cnt[i] = 0;
    }
    int total;
    int excl = block_escan256(v, tid, smem8, &total);
    if (i < N_NODES) g_row[i] = excl;
    if (tid == 0) g_bsum[blockIdx.x] = total;
}

// scan3: every block redundantly scans the 196 block sums; finalizes row/work.
__global__ void __launch_bounds__(256) scan3_kernel() {
    __shared__ int smem8[8];
    __shared__ int s_excl[256];
    int tid = threadIdx.x;
    int v = (tid < SCAN_NB) ? g_bsum[tid] : 0;
    int total;
    int excl = block_escan256(v, tid, smem8, &total);
    s_excl[tid] = excl;
    __syncthreads();
    int boff = s_excl[blockIdx.x];

    int i = blockIdx.x * 256 + tid;
    if (i < N_NODES) {
        int r = g_row[i] + boff;
        g_row[i]  = r;
        g_work[i] = r;
    }
    if (i == 0) g_row[N_NODES] = N_EDGES;
}

// ---------------------------------------------------------------------------
// FUSED: CSR scatter (blocks [0, HIST_NB)) || W convert/transpose (rest).
// ---------------------------------------------------------------------------
__global__ void __launch_bounds__(256) fused_scatter_convw_kernel(
    const int* __restrict__ src, const int* __restrict__ dst,
    const float* __restrict__ W)
{
    if (blockIdx.x < HIST_NB) {
        int t = blockIdx.x * 256 + threadIdx.x;
        if (t < N_EDGES / 4) {
            int4 s = __ldg((const int4*)src + t);
            int4 d = __ldg((const int4*)dst + t);
            g_csr[atomicAdd(&g_work[d.x], 1)] = s.x;
            g_csr[atomicAdd(&g_work[d.y], 1)] = s.y;
            g_csr[atomicAdd(&g_work[d.z], 1)] = s.z;
            g_csr[atomicAdd(&g_work[d.w], 1)] = s.w;
        }
    } else {
        int idx = (blockIdx.x - HIST_NB) * 256 + threadIdx.x;
        if (idx < D * D) {
            int k = idx >> 9, n = idx & 511;
            g_wt[(size_t)n * D + k] = __float2half_rn(W[idx]);
        }
    }
}

// ---------------------------------------------------------------------------
// Aggregation: 256-thread block = 2 nodes (128 threads each); unroll 8 for
// MLP; no smem -> full occupancy. fp16 gathers, fp32 accumulate.
// ---------------------------------------------------------------------------
__global__ void __launch_bounds__(256) agg_kernel() {
    const int tid = threadIdx.x;
    const int wg = tid >> 7;                 // 0 or 1
    const int wg_tid = tid & 127;
    const int node = blockIdx.x * 2 + wg;    // < M_PAD

    float4 acc = make_float4(0.f, 0.f, 0.f, 0.f);
    if (node < N_NODES) {
        const int s0 = g_row[node];
        const int s1 = g_row[node + 1];
        int e = s0;
        for (; e + 7 < s1; e += 8) {
            int si[8];
            #pragma unroll
            for (int j = 0; j < 8; j++) si[j] = __ldg(&g_csr[e + j]);
            uint2 v[8];
            #pragma unroll
            for (int j = 0; j < 8; j++)
                v[j] = __ldg((const uint2*)(g_x16 + (size_t)si[j] * D) + wg_tid);
            #pragma unroll
            for (int j = 0; j < 8; j++) {
                float2 f0 = __half22float2(*(__half2*)&v[j].x);
                float2 f1 = __half22float2(*(__half2*)&v[j].y);
                acc.x += f0.x; acc.y += f0.y; acc.z += f1.x; acc.w += f1.y;
            }
        }
        for (; e < s1; e++) {
            int sa = __ldg(&g_csr[e]);
            uint2 v = __ldg((const uint2*)(g_x16 + (size_t)sa * D) + wg_tid);
            float2 f0 = __half22float2(*(__half2*)&v.x);
            float2 f1 = __half22float2(*(__half2*)&v.y);
            acc.x += f0.x; acc.y += f0.y; acc.z += f1.x; acc.w += f1.y;
        }
    }
    __half h[4] = {__float2half_rn(acc.x), __float2half_rn(acc.y),
                   __float2half_rn(acc.z), __float2half_rn(acc.w)};
    *(uint2*)(g_a + (size_t)node * D + wg_tid * 4) = *(uint2*)h;
}

// ---------------------------------------------------------------------------
// mma.sync fp16 single-product GEMM: C = A @ Wt^T + bias
// CTA 128x128, BK=32, 3-stage pipeline (depth-2 prefetch, 1 sync/iter),
// 8 warps, warp tile 64x32, 2 CTAs/SM.
// ---------------------------------------------------------------------------
#define BK      32
#define KP      40                    // padded smem row stride (elements)
#define TILE_B  (128 * KP * 2)        // 10240 B per tile
#define STAGE_B (2 * TILE_B)          // A, B = 20480 B
#define STAGES  3
#define SMEM_TOTAL (STAGES * STAGE_B) // 61440 B
#define NK      (D / BK)              // 16

__global__ void __launch_bounds__(256, 2) gemm_mma_kernel(
    const float* __restrict__ bias,
    float* __restrict__ C)
{
    extern __shared__ char smem[];
    const uint32_t smem_base = smem_u32(smem);
    const int tid  = threadIdx.x;
    const int wid  = tid >> 5;
    const int lane = tid & 31;
    const int wm   = wid >> 2;
    const int wn   = wid & 3;
    const int block_m = blockIdx.y * 128;
    const int block_n = blockIdx.x * 128;

    auto load_chunk = [&](int kt, int stage) {
        const int k0 = kt * BK;
        const uint32_t sb = smem_base + stage * STAGE_B;
        #pragma unroll
        for (int it = 0; it < 4; it++) {
            const int cid  = it * 256 + tid;      // 0..1023
            const int tile = cid >> 9;            // 0..1
            const int r    = (cid >> 2) & 127;
            const int c4   = cid & 3;
            const __half* g;
            if (tile == 0) g = g_a  + (size_t)(block_m + r) * D;
            else           g = g_wt + (size_t)(block_n + r) * D;
            cp_async16(sb + tile * TILE_B + r * (KP * 2) + c4 * 16,
                       g + k0 + c4 * 8);
        }
        cp_commit();
    };

    float acc[4][4][4];
    #pragma unroll
    for (int i = 0; i < 4; i++)
        #pragma unroll
        for (int j = 0; j < 4; j++)
            #pragma unroll
            for (int e = 0; e < 4; e++)
                acc[i][j][e] = 0.f;

    load_chunk(0, 0);
    load_chunk(1, 1);

    const uint32_t row_off = (uint32_t)(lane & 15) * (KP * 2);
    const uint32_t k_lane  = (uint32_t)((lane >> 4) << 4);

    for (int kt = 0; kt < NK; kt++) {
        if (kt >= NK - 1) cp_wait<0>(); else cp_wait<1>();
        __syncthreads();
        if (kt + 2 < NK) load_chunk(kt + 2, (kt + 2) % STAGES);

        const uint32_t sb  = smem_base + (kt % STAGES) * STAGE_B;
        const uint32_t aF0 = sb + 0 * TILE_B + (wm * 64) * (KP * 2) + row_off;
        const uint32_t bF0 = sb + 1 * TILE_B + (wn * 32) * (KP * 2) + row_off;

        #pragma unroll
        for (int ks = 0; ks < 2; ks++) {
            const uint32_t koff = ks * 32 + k_lane;
            uint32_t bF[2][4];
            #pragma unroll
            for (int np = 0; np < 2; np++)
                ldm_x4(bF[np], bF0 + np * 16 * (KP * 2) + koff);
            #pragma unroll
            for (int mt = 0; mt < 4; mt++) {
                uint32_t aF[4];
                ldm_x4(aF, aF0 + mt * 16 * (KP * 2) + koff);
                #pragma unroll
                for (int nt = 0; nt < 4; nt++) {
                    const int np = nt >> 1, sel = nt & 1;
                    mma_fp16(acc[mt][nt], aF, bF[np][sel], bF[np][sel + 2]);
                }
            }
        }
    }

    #pragma unroll
    for (int nt = 0; nt < 4; nt++) {
        const int col = block_n + wn * 32 + nt * 8 + (lane & 3) * 2;
        const float2 bv = *(const float2*)(bias + col);
        #pragma unroll
        for (int mt = 0; mt < 4; mt++) {
            const int r0 = block_m + wm * 64 + mt * 16 + (lane >> 2);
            const int r1 = r0 + 8;
            if (r0 < N_NODES) {
                float2 o = make_float2(acc[mt][nt][0] + bv.x,
                                       acc[mt][nt][1] + bv.y);
                *(float2*)(C + (size_t)r0 * D + col) = o;
            }
            if (r1 < N_NODES) {
                float2 o = make_float2(acc[mt][nt][2] + bv.x,
                                       acc[mt][nt][3] + bv.y);
                *(float2*)(C + (size_t)r1 * D + col) = o;
            }
        }
    }
}

// ---------------------------------------------------------------------------
extern "C" void kernel_launch(void* const* d_in, const int* in_sizes, int n_in,
                              void* d_out, int out_size)
{
    const float* x      = (const float*)d_in[0];
    const float* weight = (const float*)d_in[1];
    const float* bias   = (const float*)d_in[2];
    const int*   src    = (const int*)d_in[3];
    const int*   dst    = (const int*)d_in[4];
    float*       out    = (float*)d_out;

    fused_hist_convx_kernel<<<HIST_NB + CONVX_NB, 256>>>(dst, x);
    scan1_kernel<<<SCAN_NB, 256>>>();
    scan3_kernel<<<SCAN_NB, 256>>>();
    fused_scatter_convw_kernel<<<HIST_NB + CONVW_NB, 256>>>(src, dst, weight);

    agg_kernel<<<M_PAD / 2, 256>>>();

    {
        static bool attr_set = false;
        if (!attr_set) {
            cudaFuncSetAttribute(gemm_mma_kernel,
                                 cudaFuncAttributeMaxDynamicSharedMemorySize,
                                 SMEM_TOTAL);
            attr_set = true;
        }
        dim3 grid(D / 128, M_PAD / 128);  // (4, 391)
        gemm_mma_kernel<<<grid, 256, SMEM_TOTAL>>>(bias, out);
    }
}

// round 17
// speedup vs baseline: 2.0283x; 1.0012x over previous
#include <cuda_runtime.h>
#include <cuda_fp16.h>
#include <stdint.h>

// GCNConvDGL: out = segment_sum(x[src] -> dst) @ W + bias
// Fused CSR build (single-pass coop scan) + fp16 aggregation + fp16 GEMM.

#define N_NODES 50000
#define N_EDGES 800000
#define D       512
#define M_PAD   50048          // 391 * 128
#define SCAN_NB 196            // ceil(50000 / 256)
#define HIST_NB 782            // ceil(200000 / 256)  (int4 edge chunks)
#define CONVX_NB 25000         // 25.6M elems / 4 per thread / 256 threads
#define CONVW_NB 1024          // 512*512/256

// ---------------- scratch (static device globals) ----------------
__device__ __half  g_x16[(size_t)N_NODES * D];  // 51.2 MB
__device__ __half  g_a[(size_t)M_PAD * D];      // 51.2 MB
__device__ __half  g_wt[(size_t)D * D];         // W^T fp16
__device__ int     g_cnt[N_NODES];              // zero at entry (zero-init; scan re-zeroes)
__device__ int     g_row[N_NODES + 1];
__device__ int     g_work[N_NODES];
__device__ int     g_csr[N_EDGES];
__device__ int     g_bsum[SCAN_NB];
__device__ int     g_bflag[SCAN_NB];            // zero at entry; reset by scatter kernel

// ---------------- PTX helpers ----------------
__device__ __forceinline__ uint32_t smem_u32(const void* p) {
    uint32_t a;
    asm("{ .reg .u64 t; cvta.to.shared.u64 t, %1; cvt.u32.u64 %0, t; }"
        : "=r"(a) : "l"(p));
    return a;
}
__device__ __forceinline__ void cp_async16(uint32_t saddr, const void* gaddr) {
    asm volatile("cp.async.cg.shared.global [%0], [%1], 16;"
                 :: "r"(saddr), "l"(gaddr) : "memory");
}
__device__ __forceinline__ void cp_commit() {
    asm volatile("cp.async.commit_group;" ::: "memory");
}
template <int N> __device__ __forceinline__ void cp_wait() {
    asm volatile("cp.async.wait_group %0;" :: "n"(N) : "memory");
}
__device__ __forceinline__ void ldm_x4(uint32_t* r, uint32_t saddr) {
    asm volatile("ldmatrix.sync.aligned.m8n8.x4.shared.b16 {%0,%1,%2,%3}, [%4];"
                 : "=r"(r[0]), "=r"(r[1]), "=r"(r[2]), "=r"(r[3])
                 : "r"(saddr));
}
__device__ __forceinline__ void mma_fp16(float* c, const uint32_t* a,
                                         uint32_t b0, uint32_t b1) {
    asm volatile(
        "mma.sync.aligned.m16n8k16.row.col.f32.f16.f16.f32 "
        "{%0,%1,%2,%3}, {%4,%5,%6,%7}, {%8,%9}, {%0,%1,%2,%3};"
        : "+f"(c[0]), "+f"(c[1]), "+f"(c[2]), "+f"(c[3])
        : "r"(a[0]), "r"(a[1]), "r"(a[2]), "r"(a[3]), "r"(b0), "r"(b1));
}
__device__ __forceinline__ float4 ld_cs_f4(const float* p) {
    float4 v;
    asm volatile("ld.global.cs.v4.f32 {%0, %1, %2, %3}, [%4];"
                 : "=f"(v.x), "=f"(v.y), "=f"(v.z), "=f"(v.w) : "l"(p));
    return v;
}
__device__ __forceinline__ int ld_acquire(const int* p) {
    int v;
    asm volatile("ld.acquire.gpu.s32 %0, [%1];" : "=r"(v) : "l"(p));
    return v;
}

// Warp-inclusive scan
__device__ __forceinline__ int warp_iscan(int v, int lane) {
    #pragma unroll
    for (int off = 1; off < 32; off <<= 1) {
        int t = __shfl_up_sync(0xFFFFFFFF, v, off);
        if (lane >= off) v += t;
    }
    return v;
}

__device__ __forceinline__ int block_escan256(int v, int tid, int* smem8, int* total) {
    const int lane = tid & 31, wid = tid >> 5;
    int inc = warp_iscan(v, lane);
    if (lane == 31) smem8[wid] = inc;
    __syncthreads();
    if (wid == 0) {
        int ws = (lane < 8) ? smem8[lane] : 0;
        ws = warp_iscan(ws, lane);
        if (lane < 8) smem8[lane] = ws;
    }
    __syncthreads();
    int woff = (wid > 0) ? smem8[wid - 1] : 0;
    *total = smem8[7];
    return inc - v + woff;
}

// ---------------------------------------------------------------------------
// FUSED: dst-histogram (blocks [0, HIST_NB)) || x fp32->fp16 convert (rest).
// ---------------------------------------------------------------------------
__global__ void __launch_bounds__(256) fused_hist_convx_kernel(
    const int* __restrict__ dst, const float* __restrict__ x)
{
    if (blockIdx.x < HIST_NB) {
        int t = blockIdx.x * 256 + threadIdx.x;
        if (t < N_EDGES / 4) {
            int4 d = __ldg((const int4*)dst + t);
            atomicAdd(&g_cnt[d.x], 1);
            atomicAdd(&g_cnt[d.y], 1);
            atomicAdd(&g_cnt[d.z], 1);
            atomicAdd(&g_cnt[d.w], 1);
        }
    } else {
        size_t i = ((size_t)(blockIdx.x - HIST_NB) * 256 + threadIdx.x) * 4;
        if (i < (size_t)N_NODES * D) {
            float4 v = ld_cs_f4(x + i);
            __half h[4] = {__float2half_rn(v.x), __float2half_rn(v.y),
                           __float2half_rn(v.z), __float2half_rn(v.w)};
            *(uint2*)(g_x16 + i) = *(uint2*)h;
        }
    }
}

// ---------------------------------------------------------------------------
// Single-pass cooperative scan (196 blocks, all co-resident):
//   1. block-local exclusive scan of its 256 counts (re-zeroes g_cnt)
//   2. publish block total (fence + flag)
//   3. spin until all 196 totals published, scan them in smem
//   4. write final g_row / g_work
// g_bflag reset to 0 by the NEXT kernel (fused_scatter_convw), preserving
// determinism across graph replays.
// ---------------------------------------------------------------------------
__global__ void __launch_bounds__(256) scan_fused_kernel() {
    __shared__ int smem8[8];
    __shared__ int s_excl[256];
    const int tid = threadIdx.x;
    const int b = blockIdx.x;
    const int i = b * 256 + tid;

    int v = 0;
    if (i < N_NODES) {
        v = g_cnt[i];
        g_cnt[i] = 0;
    }
    int total;
    int excl = block_escan256(v, tid, smem8, &total);

    if (tid == 0) {
        g_bsum[b] = total;
        __threadfence();
        atomicExch(&g_bflag[b], 1);
    }

    // gather all block sums (spin until published)
    int bv = 0;
    if (tid < SCAN_NB) {
        while (ld_acquire(&g_bflag[tid]) == 0) __nanosleep(64);
        bv = g_bsum[tid];
    }
    __syncthreads();   // protect smem8 reuse across the two scans

    int t2;
    int excl2 = block_escan256(bv, tid, smem8, &t2);
    s_excl[tid] = excl2;
    __syncthreads();
    const int boff = s_excl[b];

    if (i < N_NODES) {
        int r = excl + boff;
        g_row[i]  = r;
        g_work[i] = r;
    }
    if (i == 0) g_row[N_NODES] = N_EDGES;
}

// ---------------------------------------------------------------------------
// FUSED: CSR scatter (blocks [0, HIST_NB)) || W convert/transpose (rest).
// First convw block also resets g_bflag for the next replay.
// ---------------------------------------------------------------------------
__global__ void __launch_bounds__(256) fused_scatter_convw_kernel(
    const int* __restrict__ src, const int* __restrict__ dst,
    const float* __restrict__ W)
{
    if (blockIdx.x < HIST_NB) {
        int t = blockIdx.x * 256 + threadIdx.x;
        if (t < N_EDGES / 4) {
            int4 s = __ldg((const int4*)src + t);
            int4 d = __ldg((const int4*)dst + t);
            g_csr[atomicAdd(&g_work[d.x], 1)] = s.x;
            g_csr[atomicAdd(&g_work[d.y], 1)] = s.y;
            g_csr[atomicAdd(&g_work[d.z], 1)] = s.z;
            g_csr[atomicAdd(&g_work[d.w], 1)] = s.w;
        }
    } else {
        int idx = (blockIdx.x - HIST_NB) * 256 + threadIdx.x;
        if (blockIdx.x == HIST_NB && threadIdx.x < SCAN_NB)
            g_bflag[threadIdx.x] = 0;          // reset for next replay
        if (idx < D * D) {
            int k = idx >> 9, n = idx & 511;
            g_wt[(size_t)n * D + k] = __float2half_rn(W[idx]);
        }
    }
}

// ---------------------------------------------------------------------------
// Aggregation: 256-thread block = 2 nodes (128 threads each); unroll 8.
// ---------------------------------------------------------------------------
__global__ void __launch_bounds__(256) agg_kernel() {
    const int tid = threadIdx.x;
    const int wg = tid >> 7;
    const int wg_tid = tid & 127;
    const int node = blockIdx.x * 2 + wg;

    float4 acc = make_float4(0.f, 0.f, 0.f, 0.f);
    if (node < N_NODES) {
        const int s0 = g_row[node];
        const int s1 = g_row[node + 1];
        int e = s0;
        for (; e + 7 < s1; e += 8) {
            int si[8];
            #pragma unroll
            for (int j = 0; j < 8; j++) si[j] = __ldg(&g_csr[e + j]);
            uint2 v[8];
            #pragma unroll
            for (int j = 0; j < 8; j++)
                v[j] = __ldg((const uint2*)(g_x16 + (size_t)si[j] * D) + wg_tid);
            #pragma unroll
            for (int j = 0; j < 8; j++) {
                float2 f0 = __half22float2(*(__half2*)&v[j].x);
                float2 f1 = __half22float2(*(__half2*)&v[j].y);
                acc.x += f0.x; acc.y += f0.y; acc.z += f1.x; acc.w += f1.y;
            }
        }
        for (; e < s1; e++) {
            int sa = __ldg(&g_csr[e]);
            uint2 v = __ldg((const uint2*)(g_x16 + (size_t)sa * D) + wg_tid);
            float2 f0 = __half22float2(*(__half2*)&v.x);
            float2 f1 = __half22float2(*(__half2*)&v.y);
            acc.x += f0.x; acc.y += f0.y; acc.z += f1.x; acc.w += f1.y;
        }
    }
    __half h[4] = {__float2half_rn(acc.x), __float2half_rn(acc.y),
                   __float2half_rn(acc.z), __float2half_rn(acc.w)};
    *(uint2*)(g_a + (size_t)node * D + wg_tid * 4) = *(uint2*)h;
}

// ---------------------------------------------------------------------------
// mma.sync fp16 single-product GEMM: C = A @ Wt^T + bias
// CTA 128x128, BK=32, 3-stage pipeline, 8 warps, warp tile 64x32, 2 CTAs/SM.
// ---------------------------------------------------------------------------
#define BK      32
#define KP      40                    // padded smem row stride (elements)
#define TILE_B  (128 * KP * 2)        // 10240 B per tile
#define STAGE_B (2 * TILE_B)          // A, B = 20480 B
#define STAGES  3
#define SMEM_TOTAL (STAGES * STAGE_B) // 61440 B
#define NK      (D / BK)              // 16

__global__ void __launch_bounds__(256, 2) gemm_mma_kernel(
    const float* __restrict__ bias,
    float* __restrict__ C)
{
    extern __shared__ char smem[];
    const uint32_t smem_base = smem_u32(smem);
    const int tid  = threadIdx.x;
    const int wid  = tid >> 5;
    const int lane = tid & 31;
    const int wm   = wid >> 2;
    const int wn   = wid & 3;
    const int block_m = blockIdx.y * 128;
    const int block_n = blockIdx.x * 128;

    auto load_chunk = [&](int kt, int stage) {
        const int k0 = kt * BK;
        const uint32_t sb = smem_base + stage * STAGE_B;
        #pragma unroll
        for (int it = 0; it < 4; it++) {
            const int cid  = it * 256 + tid;      // 0..1023
            const int tile = cid >> 9;            // 0..1
            const int r    = (cid >> 2) & 127;
            const int c4   = cid & 3;
            const __half* g;
            if (tile == 0) g = g_a  + (size_t)(block_m + r) * D;
            else           g = g_wt + (size_t)(block_n + r) * D;
            cp_async16(sb + tile * TILE_B + r * (KP * 2) + c4 * 16,
                       g + k0 + c4 * 8);
        }
        cp_commit();
    };

    float acc[4][4][4];
    #pragma unroll
    for (int i = 0; i < 4; i++)
        #pragma unroll
        for (int j = 0; j < 4; j++)
            #pragma unroll
            for (int e = 0; e < 4; e++)
                acc[i][j][e] = 0.f;

    load_chunk(0, 0);
    load_chunk(1, 1);

    const uint32_t row_off = (uint32_t)(lane & 15) * (KP * 2);
    const uint32_t k_lane  = (uint32_t)((lane >> 4) << 4);

    for (int kt = 0; kt < NK; kt++) {
        if (kt >= NK - 1) cp_wait<0>(); else cp_wait<1>();
        __syncthreads();
        if (kt + 2 < NK) load_chunk(kt + 2, (kt + 2) % STAGES);

        const uint32_t sb  = smem_base + (kt % STAGES) * STAGE_B;
        const uint32_t aF0 = sb + 0 * TILE_B + (wm * 64) * (KP * 2) + row_off;
        const uint32_t bF0 = sb + 1 * TILE_B + (wn * 32) * (KP * 2) + row_off;

        #pragma unroll
        for (int ks = 0; ks < 2; ks++) {
            const uint32_t koff = ks * 32 + k_lane;
            uint32_t bF[2][4];
            #pragma unroll
            for (int np = 0; np < 2; np++)
                ldm_x4(bF[np], bF0 + np * 16 * (KP * 2) + koff);
            #pragma unroll
            for (int mt = 0; mt < 4; mt++) {
                uint32_t aF[4];
                ldm_x4(aF, aF0 + mt * 16 * (KP * 2) + koff);
                #pragma unroll
                for (int nt = 0; nt < 4; nt++) {
                    const int np = nt >> 1, sel = nt & 1;
                    mma_fp16(acc[mt][nt], aF, bF[np][sel], bF[np][sel + 2]);
                }
            }
        }
    }

    #pragma unroll
    for (int nt = 0; nt < 4; nt++) {
        const int col = block_n + wn * 32 + nt * 8 + (lane & 3) * 2;
        const float2 bv = *(const float2*)(bias + col);
        #pragma unroll
        for (int mt = 0; mt < 4; mt++) {
            const int r0 = block_m + wm * 64 + mt * 16 + (lane >> 2);
            const int r1 = r0 + 8;
            if (r0 < N_NODES) {
                float2 o = make_float2(acc[mt][nt][0] + bv.x,
                                       acc[mt][nt][1] + bv.y);
                *(float2*)(C + (size_t)r0 * D + col) = o;
            }
            if (r1 < N_NODES) {
                float2 o = make_float2(acc[mt][nt][2] + bv.x,
                                       acc[mt][nt][3] + bv.y);
                *(float2*)(C + (size_t)r1 * D + col) = o;
            }
        }
    }
}

// ---------------------------------------------------------------------------
extern "C" void kernel_launch(void* const* d_in, const int* in_sizes, int n_in,
                              void* d_out, int out_size)
{
    const float* x      = (const float*)d_in[0];
    const float* weight = (const float*)d_in[1];
    const float* bias   = (const float*)d_in[2];
    const int*   src    = (const int*)d_in[3];
    const int*   dst    = (const int*)d_in[4];
    float*       out    = (float*)d_out;

    fused_hist_convx_kernel<<<HIST_NB + CONVX_NB, 256>>>(dst, x);
    scan_fused_kernel<<<SCAN_NB, 256>>>();
    fused_scatter_convw_kernel<<<HIST_NB + CONVW_NB, 256>>>(src, dst, weight);

    agg_kernel<<<M_PAD / 2, 256>>>();

    {
        static bool attr_set = false;
        if (!attr_set) {
            cudaFuncSetAttribute(gemm_mma_kernel,
                                 cudaFuncAttributeMaxDynamicSharedMemorySize,
                                 SMEM_TOTAL);
            attr_set = true;
        }
        dim3 grid(D / 128, M_PAD / 128);  // (4, 391)
        gemm_mma_kernel<<<grid, 256, SMEM_TOTAL>>>(bias, out);
    }
}